// round 17
// baseline (speedup 1.0000x reference)
#include <cuda_runtime.h>
#include <cuda_bf16.h>
#include <cstdint>

#define BATCH 128
#define SEQ   512
#define IDIM  256
#define HDIM  512
#define G4    2048

// ---- scan geometry: 128 CTAs = 2 batch-tiles(64) x 64 j-tiles(8 j) ----
#define NBLK  128
#define NTHR  512      // 16 warps = kh(4) x mg(4, m16 each)
#define BJ    8
#define BB    64

// ---- scan SMEM layout (bytes) ----
#define BROW   1040
#define SB_H   0
#define SB_L   41600
#define SA     83200          // A chunk bufs: 2 x 4 arrays x 64 rows x 272B
#define AROWB  272
#define AARR   17408
#define ABUF   69632
#define SMEM_SCAN 222464
#define RSETK  2624           // 64*41 floats

// ---- u_gemm v3 SMEM layout (bytes): K chunks of 32, 84KB -> 2 CTAs/SM ----
#define UFS_X  0
#define UFS_U  36864
#define UBA    55296
#define UBB    75776
#define UG_SMEM 86016

// ---- device-global scratch ----
__device__ __nv_bfloat16 g_hh[2][BATCH][HDIM];
__device__ __nv_bfloat16 g_hl[2][BATCH][HDIM];
__device__ __nv_bfloat16 g_ch[2][BATCH][HDIM];
__device__ __nv_bfloat16 g_cl[2][BATCH][HDIM];
__device__ float g_c[2][BATCH][HDIM];
__device__ float g_u[SEQ][BATCH][G4];
__device__ unsigned g_barx[8 * 32];
__device__ unsigned g_barroot[64];

// ---- helpers ----
static __device__ __forceinline__ uint32_t smem_u32(const void* p) {
    uint32_t a;
    asm("{ .reg .u64 t; cvta.to.shared.u64 t, %1; cvt.u32.u64 %0, t; }" : "=r"(a) : "l"(p));
    return a;
}
__device__ __forceinline__ void ldsm4(unsigned* r, uint32_t a) {
    asm volatile("ldmatrix.sync.aligned.m8n8.x4.shared.b16 {%0,%1,%2,%3}, [%4];"
        : "=r"(r[0]), "=r"(r[1]), "=r"(r[2]), "=r"(r[3]) : "r"(a));
}
__device__ __forceinline__ void ldsm2(unsigned* r, uint32_t a) {
    asm volatile("ldmatrix.sync.aligned.m8n8.x2.shared.b16 {%0,%1}, [%2];"
        : "=r"(r[0]), "=r"(r[1]) : "r"(a));
}
__device__ __forceinline__ void mma16816(float* d, const unsigned* a, const unsigned* b) {
    asm volatile("mma.sync.aligned.m16n8k16.row.col.f32.bf16.bf16.f32 "
        "{%0,%1,%2,%3}, {%4,%5,%6,%7}, {%8,%9}, {%0,%1,%2,%3};"
        : "+f"(d[0]), "+f"(d[1]), "+f"(d[2]), "+f"(d[3])
        : "r"(a[0]), "r"(a[1]), "r"(a[2]), "r"(a[3]), "r"(b[0]), "r"(b[1]));
}
__device__ __forceinline__ void cpa16(uint32_t dst, const void* src) {
    asm volatile("cp.async.cg.shared.global [%0], [%1], 16;" :: "r"(dst), "l"(src));
}
#define CP_COMMIT() asm volatile("cp.async.commit_group;" ::: "memory")
#define CP_WAIT(n)  asm volatile("cp.async.wait_group %0;" :: "n"(n) : "memory")

__device__ __forceinline__ float sigm(float x) { return 1.0f / (1.0f + __expf(-x)); }
__device__ __forceinline__ float tanhfast(float x) {
    float y;
    asm("tanh.approx.f32 %0, %1;" : "=f"(y) : "f"(x));
    return y;
}
__device__ __forceinline__ unsigned pack2(float a, float b) {
    return (unsigned)__bfloat16_as_ushort(__float2bfloat16(a)) |
           ((unsigned)__bfloat16_as_ushort(__float2bfloat16(b)) << 16);
}
__device__ __forceinline__ void hilo2(float a, float b, unsigned& hi, unsigned& lo) {
    __nv_bfloat16 ah = __float2bfloat16(a), bh = __float2bfloat16(b);
    hi = (unsigned)__bfloat16_as_ushort(ah) | ((unsigned)__bfloat16_as_ushort(bh) << 16);
    lo = pack2(a - __bfloat162float(ah), b - __bfloat162float(bh));
}

// =====================================================================
// Kernel 1 v3: u_pre = X @ U^T + Ub + Wallb (unchanged from R16)
// =====================================================================
__global__ void __launch_bounds__(256, 2)
u_gemm_mma(const float* __restrict__ X, const float* __restrict__ Uw,
           const float* __restrict__ Ub, const float* __restrict__ Wb) {
    extern __shared__ char smc[];
    const uint32_t smb = smem_u32(smc);
    const int tid  = threadIdx.x;
    const int lane = tid & 31;
    const int wid  = tid >> 5;
    const int g0 = blockIdx.x * 64;
    const int r0 = blockIdx.y * 128;

    auto stage = [&](int q, int b) {
#pragma unroll
        for (int t = 0; t < 4; ++t) {
            int idx = tid + t * 256;
            int row = idx >> 3, seg = idx & 7;
            cpa16(smb + UFS_X + b * 18432 + row * 144 + seg * 16,
                  &X[(size_t)(r0 + row) * IDIM + q * 32 + seg * 4]);
        }
#pragma unroll
        for (int t = 0; t < 2; ++t) {
            int idx = tid + t * 256;
            int row = idx >> 3, seg = idx & 7;
            cpa16(smb + UFS_U + b * 9216 + row * 144 + seg * 16,
                  &Uw[(size_t)(g0 + row) * IDIM + q * 32 + seg * 4]);
        }
    };

    stage(0, 0); CP_COMMIT();
    stage(1, 1); CP_COMMIT();

    const uint32_t aoff = ((lane & 7) + ((lane >> 3) & 1) * 8) * 80 + (lane >> 4) * 16;
    const uint32_t boff = (lane & 7) * 80 + ((lane >> 3) & 1) * 16 + (lane >> 4) * (8 * 80);
    const uint32_t awoff = (uint32_t)(wid * 16) * 80 + aoff;

    float d[8][4] = {};

#pragma unroll 1
    for (int q = 0; q < 8; ++q) {
        const int buf = q & 1;
        if (q < 7) { CP_WAIT(1); } else { CP_WAIT(0); }
        __syncthreads();

#pragma unroll
        for (int t = 0; t < 4; ++t) {
            int idx = tid + t * 256;
            int row = idx >> 3, seg = idx & 7;
            float4 w = *(const float4*)(smc + UFS_X + buf * 18432 + row * 144 + seg * 16);
            unsigned h0, l0, h1, l1;
            hilo2(w.x, w.y, h0, l0);
            hilo2(w.z, w.w, h1, l1);
            *(uint2*)(smc + UBA + row * 80 + seg * 8)         = make_uint2(h0, h1);
            *(uint2*)(smc + UBA + 10240 + row * 80 + seg * 8) = make_uint2(l0, l1);
        }
#pragma unroll
        for (int t = 0; t < 2; ++t) {
            int idx = tid + t * 256;
            int row = idx >> 3, seg = idx & 7;
            float4 w = *(const float4*)(smc + UFS_U + buf * 9216 + row * 144 + seg * 16);
            unsigned h0, l0, h1, l1;
            hilo2(w.x, w.y, h0, l0);
            hilo2(w.z, w.w, h1, l1);
            *(uint2*)(smc + UBB + row * 80 + seg * 8)        = make_uint2(h0, h1);
            *(uint2*)(smc + UBB + 5120 + row * 80 + seg * 8) = make_uint2(l0, l1);
        }
        __syncthreads();

        if (q < 6) { stage(q + 2, buf); CP_COMMIT(); }

#pragma unroll
        for (int ksl = 0; ksl < 2; ++ksl) {
            const uint32_t kb = ksl * 32;
            unsigned ah[4], al[4], bh[16], bl[16];
            ldsm4(ah, smb + UBA + awoff + kb);
            ldsm4(al, smb + UBA + 10240 + awoff + kb);
#pragma unroll
            for (int n4 = 0; n4 < 4; ++n4) {
                ldsm4(&bh[n4 * 4], smb + UBB + n4 * (16 * 80) + boff + kb);
                ldsm4(&bl[n4 * 4], smb + UBB + 5120 + n4 * (16 * 80) + boff + kb);
            }
#pragma unroll
            for (int nt = 0; nt < 8; ++nt) {
                const unsigned* fh = &bh[(nt >> 1) * 4 + (nt & 1) * 2];
                const unsigned* fl = &bl[(nt >> 1) * 4 + (nt & 1) * 2];
                mma16816(d[nt], ah, fh);
                mma16816(d[nt], ah, fl);
                mma16816(d[nt], al, fh);
            }
        }
        __syncthreads();
    }

    const int tid4 = lane & 3, gid = lane >> 2;
#pragma unroll
    for (int nt = 0; nt < 8; ++nt) {
        const int gb = g0 + nt * 8 + tid4 * 2;
        float2 bias = make_float2(Ub[gb] + Wb[gb], Ub[gb + 1] + Wb[gb + 1]);
#pragma unroll
        for (int h = 0; h < 2; ++h) {
            const int r = r0 + wid * 16 + gid + h * 8;
            const int b = r >> 9, s = r & 511;
            float2 v = make_float2(d[nt][h * 2] + bias.x, d[nt][h * 2 + 1] + bias.y);
            *(float2*)&g_u[s][b][gb] = v;
        }
    }
}

// =====================================================================
// Kernel 2: mma.sync scan, 512 threads (16 warps = kh4 x mg4, m16/warp).
// Doubles warps/SMSP for latency hiding; per-warp accum 20 regs.
// Epilogue: 1 batch x 1 j per thread. Rest identical to R16.
// =====================================================================
__global__ void __launch_bounds__(NTHR, 1)
timelstm_scan_mma(const float* __restrict__ Wall, const float* __restrict__ Wd,
                  const float* __restrict__ Wdb,  const float* __restrict__ ts,
                  float* __restrict__ out) {
    extern __shared__ char smc[];
    const uint32_t smb = smem_u32(smc);
    float* sred = (float*)(smc + SA);

    const int tid  = threadIdx.x;
    const int lane = tid & 31;
    const int wid  = tid >> 5;
    const int kh   = wid >> 2;           // 0..3 k-slice
    const int mg   = wid & 3;            // 0..3 m16 tile
    const int jt = blockIdx.x >> 1;
    const int bt = blockIdx.x & 1;
    const int j0 = jt * BJ;
    const int b0 = bt * BB;
    const int gslot = (bt * 4 + (jt >> 4)) * 32;
    const int rslot = bt * 32;

    for (int idx = tid; idx < 40 * 128; idx += NTHR) {
        int n = idx >> 7;
        int k = (idx & 127) << 2;
        const float* sp = (n < 32)
            ? &Wall[(size_t)((n >> 3) * HDIM + j0 + (n & 7)) * HDIM + k]
            : &Wd[(size_t)(j0 + n - 32) * HDIM + k];
        float4 w = *(const float4*)sp;
        unsigned h0, l0, h1, l1;
        hilo2(w.x, w.y, h0, l0);
        hilo2(w.z, w.w, h1, l1);
        *(uint2*)(smc + SB_H + n * BROW + k * 2) = make_uint2(h0, h1);
        *(uint2*)(smc + SB_L + n * BROW + k * 2) = make_uint2(l0, l1);
    }

    const int tid4 = lane & 3, gid = lane >> 2;
    // epilogue ownership: 1 batch x 1 j per thread
    const int bl_e = tid >> 3;                 // 0..63
    const int jj_e = tid & 7;                  // 0..7
    const int b_e  = b0 + bl_e;
    const float bdv = Wdb[j0 + jj_e];
    __syncthreads();

    const uint32_t aoff = ((lane & 7) + ((lane >> 3) & 1) * 8) * AROWB + (lane >> 4) * 16;
    const uint32_t boff = (lane & 7) * BROW + ((lane >> 3) & 1) * 16 + (lane >> 4) * (8 * BROW);
    const uint32_t doff = (lane & 7) * BROW + ((lane >> 3) & 1) * 16;

    const char* gsrc[4];
    gsrc[0] = (const char*)g_hh; gsrc[1] = (const char*)g_hl;
    gsrc[2] = (const char*)g_ch; gsrc[3] = (const char*)g_cl;

    for (int s = 0; s < SEQ; ++s) {
        const int cur = s & 1, nxt = cur ^ 1;
        const size_t curoff = (size_t)cur * BATCH * HDIM * 2;

        // ---- chunk-0 staging FIRST, then epilogue-operand prefetch ----
#pragma unroll
        for (int t = 0; t < 8; ++t) {
            int idx = tid + t * NTHR;
            int arr = idx >> 10, rem = idx & 1023;
            int row = rem >> 4, seg = rem & 15;
            cpa16(smb + SA + arr * AARR + row * AROWB + seg * 16,
                  gsrc[arr] + curoff + (size_t)(b0 + row) * 1024 + seg * 16);
        }
        CP_COMMIT();

        const float* ub = &g_u[s][b_e][0];
        float uF = __ldcg(ub + 0 * HDIM + j0 + jj_e);
        float uI = __ldcg(ub + 1 * HDIM + j0 + jj_e);
        float uO = __ldcg(ub + 2 * HDIM + j0 + jj_e);
        float uC = __ldcg(ub + 3 * HDIM + j0 + jj_e);
        float co = __ldcg(&g_c[cur][b_e][j0 + jj_e]);
        const float tv = __ldcg(&ts[(size_t)b_e * SEQ + s]);

        float dG[4][4] = {};
        float dD[4] = {};

#pragma unroll 1
        for (int q = 0; q < 4; ++q) {
            const int buf = q & 1;
            if (q < 3) {
                const int nb = buf ^ 1;
#pragma unroll
                for (int t = 0; t < 8; ++t) {
                    int idx = tid + t * NTHR;
                    int arr = idx >> 10, rem = idx & 1023;
                    int row = rem >> 4, seg = rem & 15;
                    cpa16(smb + SA + nb * ABUF + arr * AARR + row * AROWB + seg * 16,
                          gsrc[arr] + curoff + (size_t)(b0 + row) * 1024 + (q + 1) * 256 + seg * 16);
                }
                CP_COMMIT();
                CP_WAIT(1);
            } else {
                CP_WAIT(0);
            }
            __syncthreads();

            const uint32_t abase = smb + SA + buf * ABUF;
#pragma unroll
            for (int kk = 0; kk < 2; ++kk) {
                const int ksl = kh * 2 + kk;
                const uint32_t kbA = ksl * 32;
                const uint32_t kbB = q * 256 + ksl * 32;

                unsigned gh[8], gl[8], dh[2], dl[2];
                ldsm4(&gh[0], smb + SB_H + 0     + boff + kbB);
                ldsm4(&gh[4], smb + SB_H + 16640 + boff + kbB);
                ldsm4(&gl[0], smb + SB_L + 0     + boff + kbB);
                ldsm4(&gl[4], smb + SB_L + 16640 + boff + kbB);
                ldsm2(dh, smb + SB_H + 33280 + doff + kbB);
                ldsm2(dl, smb + SB_L + 33280 + doff + kbB);

                const uint32_t rbase = (uint32_t)(mg * 16) * AROWB + kbA + aoff;
                unsigned ah[4], al[4], ch[4], cl[4];
                ldsm4(ah, abase + 0 * AARR + rbase);
                ldsm4(al, abase + 1 * AARR + rbase);
                ldsm4(ch, abase + 2 * AARR + rbase);
                ldsm4(cl, abase + 3 * AARR + rbase);
#pragma unroll
                for (int nt = 0; nt < 4; ++nt) {
                    mma16816(dG[nt], ah, &gh[nt * 2]);
                    mma16816(dG[nt], ah, &gl[nt * 2]);
                    mma16816(dG[nt], al, &gh[nt * 2]);
                }
                mma16816(dD, ch, dh);
                mma16816(dD, ch, dl);
                mma16816(dD, cl, dh);
            }
            if (q < 3) __syncthreads();
        }

        // ---- publish partials (sred = buf0; q=3 read buf1) ----
        {
            float* rk = sred + kh * RSETK;
            const int blr = mg * 16 + gid;
#pragma unroll
            for (int fr = 0; fr < 4; ++fr) {
                const int row = blr + (fr >> 1) * 8;
                const int cp = tid4 * 2 + (fr & 1);
                float* rr = rk + row * 41;
#pragma unroll
                for (int nt = 0; nt < 4; ++nt)
                    rr[nt * 8 + cp] = dG[nt][fr];
                rr[32 + cp] = dD[fr];
            }
        }
        __syncthreads();

        float hnv;
        {
            float F = 0.f, I_ = 0.f, O_ = 0.f, Ct = 0.f, Dd = 0.f;
#pragma unroll
            for (int k4 = 0; k4 < 4; ++k4) {
                const float* rr = sred + k4 * RSETK + bl_e * 41;
                F  += rr[jj_e];
                I_ += rr[8 + jj_e];
                O_ += rr[16 + jj_e];
                Ct += rr[24 + jj_e];
                Dd += rr[32 + jj_e];
            }
            F  += uF;
            I_ += uI;
            O_ += uO;
            Ct += uC;
            Dd += bdv;
            float f   = sigm(F);
            float ii  = sigm(I_);
            float oo  = sigm(O_);
            float ct  = sigm(Ct);
            float cs1 = tanhfast(Dd);
            float cadj = co + cs1 * (tv - 1.0f);   // c - cs1 + cs1*t
            float cn = f * cadj + ii * ct;
            float hn = oo * tanhfast(cn);
            g_c[nxt][b_e][j0 + jj_e] = cn;
            __nv_bfloat16 hh = __float2bfloat16(hn);
            __nv_bfloat16 ch_ = __float2bfloat16(cn);
            g_hh[nxt][b_e][j0 + jj_e] = hh;
            g_hl[nxt][b_e][j0 + jj_e] = __float2bfloat16(hn - __bfloat162float(hh));
            g_ch[nxt][b_e][j0 + jj_e] = ch_;
            g_cl[nxt][b_e][j0 + jj_e] = __float2bfloat16(cn - __bfloat162float(ch_));
            hnv = hn;
        }

        // ---- per-bt barrier; out[] store overlapped with release wait ----
        __syncthreads();
        unsigned gen = 0;
        if (tid == 0) {
            gen = *(volatile unsigned*)&g_barroot[rslot + 16];
            __threadfence();
            if (atomicAdd(&g_barx[gslot], 1u) == 16u * gen + 15u) {
                if (atomicAdd(&g_barroot[rslot], 1u) == 4u * gen + 3u) {
                    __threadfence();
                    *(volatile unsigned*)&g_barroot[rslot + 16] = gen + 1u;
                }
            }
        }
        out[((size_t)b_e * SEQ + s) * HDIM + j0 + jj_e] = hnv;
        if (tid == 0) {
            volatile unsigned* vgen = &g_barroot[rslot + 16];
            while (*vgen == gen) { }
            __threadfence();
        }
        __syncthreads();
    }
}

// =====================================================================
extern "C" void kernel_launch(void* const* d_in, const int* in_sizes, int n_in,
                              void* d_out, int out_size) {
    const float* X     = (const float*)d_in[0];
    const float* T     = (const float*)d_in[1];
    const float* Wall  = (const float*)d_in[2];
    const float* Wallb = (const float*)d_in[3];
    const float* Uw    = (const float*)d_in[4];
    const float* Ubb   = (const float*)d_in[5];
    const float* Wd    = (const float*)d_in[6];
    const float* Wdb   = (const float*)d_in[7];
    float* out = (float*)d_out;

    void* p;
    cudaGetSymbolAddress(&p, g_hh); cudaMemsetAsync(p, 0, 2 * BATCH * HDIM * 2, 0);
    cudaGetSymbolAddress(&p, g_hl); cudaMemsetAsync(p, 0, 2 * BATCH * HDIM * 2, 0);
    cudaGetSymbolAddress(&p, g_ch); cudaMemsetAsync(p, 0, 2 * BATCH * HDIM * 2, 0);
    cudaGetSymbolAddress(&p, g_cl); cudaMemsetAsync(p, 0, 2 * BATCH * HDIM * 2, 0);
    cudaGetSymbolAddress(&p, g_c);  cudaMemsetAsync(p, 0, 2 * BATCH * HDIM * 4, 0);
    cudaGetSymbolAddress(&p, g_barx);    cudaMemsetAsync(p, 0, 8 * 32 * 4, 0);
    cudaGetSymbolAddress(&p, g_barroot); cudaMemsetAsync(p, 0, 64 * 4, 0);

    cudaFuncSetAttribute(u_gemm_mma,
                         cudaFuncAttributeMaxDynamicSharedMemorySize, UG_SMEM);
    dim3 ugrid(G4 / 64, (BATCH * SEQ) / 128);
    u_gemm_mma<<<ugrid, 256, UG_SMEM>>>(X, Uw, Ubb, Wallb);

    cudaFuncSetAttribute(timelstm_scan_mma,
                         cudaFuncAttributeMaxDynamicSharedMemorySize, SMEM_SCAN);
    timelstm_scan_mma<<<NBLK, NTHR, SMEM_SCAN>>>(Wall, Wd, Wdb, T, out);
}